// round 12
// baseline (speedup 1.0000x reference)
#include <cuda_runtime.h>
#include <cuda_bf16.h>
#include <cuda_fp16.h>
#include <cstdint>

// Problem dims (fixed by the dataset)
#define M_DIM 4096   // B*S tokens
#define N_DIM 4096   // OUT
#define K_DIM 4096   // IN
#define RANK 8
#define LORA_R 16
#define LORA_SCALING_C 1.0f  // 16.0/16

#define W_SCALE 512.0f       // W packed as W*512 to keep fp16 operands in normal range
#define W_INV_SCALE (1.0f / 512.0f)

#define TILE_M 128
#define TILE_N 64
#define KCHUNK 64                  // fp16 K elements per stage = 128B per row
#define NCHUNKS (K_DIM / KCHUNK)   // 64
#define NSTAGES 3
#define STAGE_A_BYTES (TILE_M * 128)          // 16384
#define STAGE_B_BYTES (TILE_N * 128)          // 8192
#define STAGE_BYTES (STAGE_A_BYTES + STAGE_B_BYTES)   // 24576
#define SMEM_TOTAL (NSTAGES * STAGE_BYTES)    // 73728 -> 3 CTAs/SM (221KB)

// Merged precompute grid split: W blocks FIRST (longest-job-first scheduling)
// (R9's measured-best config: scalar W path, 1024 W-blocks)
#define WCOMP_BLOCKS 1024          // (16 i-tiles of 256) x (64 o-tiles)
#define XPACK_BLOCKS 4096          // 16.7M elems / 16 per thread / 256 threads

// fp16 packed operands (x direct; W_tot * 512)
__device__ __align__(128) __half g_xh[(size_t)M_DIM * K_DIM];
__device__ __align__(128) __half g_wh[(size_t)N_DIM * K_DIM];

// ---------------- PTX helpers (sm_103 baseline ISA only) ----------------

__device__ __forceinline__ uint32_t smem_u32(const void* p) {
    uint32_t a;
    asm("{ .reg .u64 t; cvta.to.shared.u64 t, %1; cvt.u32.u64 %0, t; }"
        : "=r"(a) : "l"(p));
    return a;
}

__device__ __forceinline__ void ldsm4(uint32_t* r, uint32_t addr) {
    asm volatile("ldmatrix.sync.aligned.m8n8.x4.shared.b16 {%0,%1,%2,%3}, [%4];"
                 : "=r"(r[0]), "=r"(r[1]), "=r"(r[2]), "=r"(r[3]) : "r"(addr));
}

__device__ __forceinline__ void mma16816(float* c, const uint32_t* a,
                                         const uint32_t* b) {
    asm volatile(
        "mma.sync.aligned.m16n8k16.row.col.f32.f16.f16.f32 "
        "{%0,%1,%2,%3}, {%4,%5,%6,%7}, {%8,%9}, {%0,%1,%2,%3};"
        : "+f"(c[0]), "+f"(c[1]), "+f"(c[2]), "+f"(c[3])
        : "r"(a[0]), "r"(a[1]), "r"(a[2]), "r"(a[3]), "r"(b[0]), "r"(b[1]));
}

__device__ __forceinline__ void cp_async16(uint32_t dst, const void* src) {
    asm volatile("cp.async.cg.shared.global [%0], [%1], 16;"
                 :: "r"(dst), "l"(src));
}
#define CP_COMMIT() asm volatile("cp.async.commit_group;" ::: "memory")
#define CP_WAIT1()  asm volatile("cp.async.wait_group 1;" ::: "memory")

// ---------------- Merged precompute kernel (R9 measured-best) ----------------
// Blocks [0, WCOMP_BLOCKS): build W_tot*512 (FMA-bound, long) -- scheduled first
// Blocks [WCOMP_BLOCKS, ...): pack x -> fp16, 16 elems/thread for MLP

__global__ void precomp_all(const float* __restrict__ x,
                            const float* __restrict__ weight,
                            const float* __restrict__ scale_A,
                            const float* __restrict__ scale_B,
                            const float* __restrict__ g,
                            const float* __restrict__ lora_A,
                            const float* __restrict__ lora_B) {
    int b = blockIdx.x;
    int t = threadIdx.x;

    if (b >= WCOMP_BLOCKS) {
        // ---- x pack: 16 fp32 -> 16 fp16 per thread (4 independent float4 loads) ----
        int idx = ((b - WCOMP_BLOCKS) * 256 + t) * 4;   // float4 index, < 4194304
        float4 v[4];
#pragma unroll
        for (int u = 0; u < 4; u++)
            v[u] = reinterpret_cast<const float4*>(x)[idx + u];
#pragma unroll
        for (int u = 0; u < 4; u++) {
            __half2 h0 = __floats2half2_rn(v[u].x, v[u].y);
            __half2 h1 = __floats2half2_rn(v[u].z, v[u].w);
            uint2 pk;
            pk.x = *reinterpret_cast<uint32_t*>(&h0);
            pk.y = *reinterpret_cast<uint32_t*>(&h1);
            reinterpret_cast<uint2*>(g_xh)[idx + u] = pk;
        }
        return;
    }

    // ---- W_tot compute (scalar per-i; low register pressure) ----
    int bx = b & 15;                 // 16 i-tiles of 256
    int by = b >> 4;                 // 64 o-tiles of 64

    __shared__ float ag[64][8];
    __shared__ float lb[64][16];
    int i0 = bx * 256;
    int o0 = by * 64;

    for (int u = t; u < 64 * 8; u += 256) {
        int ol = u >> 3, k = u & 7;
        ag[ol][k] = scale_A[(size_t)(o0 + ol) * RANK + k] * g[k];
    }
    for (int u = t; u < 64 * 16; u += 256) {
        int ol = u >> 4, r = u & 15;
        lb[ol][r] = lora_B[(size_t)(o0 + ol) * LORA_R + r] * LORA_SCALING_C;
    }
    __syncthreads();

    int i = i0 + t;
    float sb[8], la[16];
#pragma unroll
    for (int k = 0; k < 8; k++) sb[k] = scale_B[(size_t)k * K_DIM + i];
#pragma unroll
    for (int r = 0; r < 16; r++) la[r] = lora_A[(size_t)r * K_DIM + i];

#pragma unroll 8
    for (int ol = 0; ol < 64; ol++) {
        int o = o0 + ol;
        float S = 0.0f, L = 0.0f;
#pragma unroll
        for (int k = 0; k < 8; k++) S = fmaf(ag[ol][k], sb[k], S);
#pragma unroll
        for (int r = 0; r < 16; r++) L = fmaf(lb[ol][r], la[r], L);
        float w = weight[(size_t)o * K_DIM + i];
        float tot = fmaf(w, S, L) * W_SCALE;
        g_wh[(size_t)o * K_DIM + i] = __float2half_rn(tot);
    }
}

// ---------------- GEMM kernel (mma.sync fp16, CTA tile 128x64, occ 3) ----------
// 128 threads, 4 warps in 2x2 grid (warp tile 64x32); occupancy 3.
// Prefetch cp.async issued AFTER k-step 0 so the post-barrier LSU burst does
// not delay the first MMAs of the chunk. (R11 measured-best GEMM, unchanged.)

__global__ void __launch_bounds__(128, 3) lora_gemm(float* __restrict__ out) {
    extern __shared__ char smem[];
    uint32_t sb = smem_u32(smem);
    int tid = threadIdx.x;
    int wid = tid >> 5;
    int lane = tid & 31;
    int warp_m = wid & 1;   // 2 m-blocks of 64
    int warp_n = wid >> 1;  // 2 n-blocks of 32
    int n0 = blockIdx.x * TILE_N;
    int m0 = blockIdx.y * TILE_M;

    // Per-thread cp.async addressing (one base each for A and B)
    int row0 = tid >> 3;          // 0..15
    int cc = tid & 7;             // 16B column
    uint32_t dOff = (uint32_t)(row0 * 128 + ((cc * 16) ^ ((row0 & 7) << 4)));
    const char* aSrc = reinterpret_cast<const char*>(g_xh)
                       + (size_t)(m0 + row0) * 8192 + cc * 16;
    const char* bSrc = reinterpret_cast<const char*>(g_wh)
                       + (size_t)(n0 + row0) * 8192 + cc * 16;
    // part stride: +16 rows = +2048B smem, +131072B global

    // ldmatrix lane addressing (swizzle: col16 ^= (row&7)<<4)
    uint32_t sx   = (uint32_t)((lane & 7) << 4);
    uint32_t aOff = (uint32_t)((warp_m * 64 + (lane & 15)) * 128);
    uint32_t aSel = (uint32_t)((lane >> 4) << 4);          // 0 or 16
    uint32_t bOff = (uint32_t)((warp_n * 32 + (lane & 7) + ((lane >> 4) << 3)) * 128);
    uint32_t bSel = (uint32_t)(((lane >> 3) & 1) << 4);    // 0 or 16

    float acc[4][4][4];
#pragma unroll
    for (int i = 0; i < 4; i++)
#pragma unroll
        for (int j = 0; j < 4; j++)
#pragma unroll
            for (int q = 0; q < 4; q++) acc[i][j][q] = 0.0f;

    // Prologue: chunks 0,1 into stages 0,1
#pragma unroll
    for (int s = 0; s < NSTAGES - 1; s++) {
        uint32_t sA = sb + s * STAGE_BYTES + dOff;
        uint32_t sBs = sA + STAGE_A_BYTES;
#pragma unroll
        for (int p = 0; p < 8; p++) cp_async16(sA + p * 2048, aSrc + (size_t)p * 131072);
#pragma unroll
        for (int p = 0; p < 4; p++) cp_async16(sBs + p * 2048, bSrc + (size_t)p * 131072);
        CP_COMMIT();
        aSrc += 128;
        bSrc += 128;
    }

    int stage = 0;
    int nstage = NSTAGES - 1;
    for (int chunk = 0; chunk < NCHUNKS; chunk++) {
        CP_WAIT1();            // chunk's group complete (<=1 outstanding beyond it)
        __syncthreads();       // also guards reuse of stage (chunk-1)

        uint32_t sA = sb + stage * STAGE_BYTES;
        uint32_t sB = sA + STAGE_A_BYTES;

        // ---- k-step 0 first (tensor pipe starts immediately after barrier) ----
        {
            uint32_t Af[4][4], Bf[2][4];
#pragma unroll
            for (int i = 0; i < 4; i++)
                ldsm4(Af[i], sA + aOff + i * 2048 + (aSel ^ sx));
#pragma unroll
            for (int p = 0; p < 2; p++)
                ldsm4(Bf[p], sB + bOff + p * 2048 + (bSel ^ sx));
#pragma unroll
            for (int i = 0; i < 4; i++)
#pragma unroll
                for (int j = 0; j < 4; j++)
                    mma16816(acc[i][j], Af[i], &Bf[j >> 1][(j & 1) * 2]);
        }

        // ---- prefetch chunk+2 while tensor pipe is busy ----
        if (chunk + NSTAGES - 1 < NCHUNKS) {
            uint32_t pA = sb + nstage * STAGE_BYTES + dOff;
            uint32_t pB = pA + STAGE_A_BYTES;
#pragma unroll
            for (int p = 0; p < 8; p++) cp_async16(pA + p * 2048, aSrc + (size_t)p * 131072);
#pragma unroll
            for (int p = 0; p < 4; p++) cp_async16(pB + p * 2048, bSrc + (size_t)p * 131072);
            aSrc += 128;
            bSrc += 128;
        }
        CP_COMMIT();

        // ---- k-steps 1..3 ----
#pragma unroll
        for (int s = 1; s < 4; s++) {
            uint32_t Af[4][4], Bf[2][4];
            uint32_t cb = (uint32_t)(s * 32);
#pragma unroll
            for (int i = 0; i < 4; i++)
                ldsm4(Af[i], sA + aOff + i * 2048 + ((cb + aSel) ^ sx));
#pragma unroll
            for (int p = 0; p < 2; p++)
                ldsm4(Bf[p], sB + bOff + p * 2048 + ((cb + bSel) ^ sx));
#pragma unroll
            for (int i = 0; i < 4; i++)
#pragma unroll
                for (int j = 0; j < 4; j++)
                    mma16816(acc[i][j], Af[i], &Bf[j >> 1][(j & 1) * 2]);
        }

        if (++stage == NSTAGES) stage = 0;
        if (++nstage == NSTAGES) nstage = 0;
    }

    // Epilogue: scale by 1/512 and store.
    // Fragment: c0,c1 at (row lane/4, col 2*(lane%4)+{0,1}), c2,c3 at row+8.
    int r0 = m0 + warp_m * 64 + (lane >> 2);
    int c0 = n0 + warp_n * 32 + (lane & 3) * 2;
#pragma unroll
    for (int i = 0; i < 4; i++) {
#pragma unroll
        for (int j = 0; j < 4; j++) {
            float* p0 = out + (size_t)(r0 + i * 16) * N_DIM + (c0 + j * 8);
            float* p1 = out + (size_t)(r0 + i * 16 + 8) * N_DIM + (c0 + j * 8);
            float2 v0 = make_float2(acc[i][j][0] * W_INV_SCALE,
                                    acc[i][j][1] * W_INV_SCALE);
            float2 v1 = make_float2(acc[i][j][2] * W_INV_SCALE,
                                    acc[i][j][3] * W_INV_SCALE);
            *reinterpret_cast<float2*>(p0) = v0;
            *reinterpret_cast<float2*>(p1) = v1;
        }
    }
}

// ---------------- Launch ----------------

extern "C" void kernel_launch(void* const* d_in, const int* in_sizes, int n_in,
                              void* d_out, int out_size) {
    (void)in_sizes; (void)n_in; (void)out_size;
    const float* x       = (const float*)d_in[0];
    const float* weight  = (const float*)d_in[1];
    const float* scale_A = (const float*)d_in[2];
    const float* scale_B = (const float*)d_in[3];
    const float* g       = (const float*)d_in[4];
    const float* lora_A  = (const float*)d_in[5];
    const float* lora_B  = (const float*)d_in[6];
    float* out = (float*)d_out;

    cudaFuncSetAttribute(lora_gemm, cudaFuncAttributeMaxDynamicSharedMemorySize,
                         SMEM_TOTAL);

    precomp_all<<<WCOMP_BLOCKS + XPACK_BLOCKS, 256>>>(x, weight, scale_A, scale_B,
                                                      g, lora_A, lora_B);
    lora_gemm<<<dim3(N_DIM / TILE_N, M_DIM / TILE_M), 128, SMEM_TOTAL>>>(out);
}

// round 13
// speedup vs baseline: 1.4763x; 1.4763x over previous
#include <cuda_runtime.h>
#include <cuda_bf16.h>
#include <cuda_fp16.h>
#include <cstdint>

// Problem dims (fixed by the dataset)
#define M_DIM 4096   // B*S tokens
#define N_DIM 4096   // OUT
#define K_DIM 4096   // IN
#define RANK 8
#define LORA_R 16
#define LORA_SCALING_C 1.0f  // 16.0/16

#define W_SCALE 512.0f       // W packed as W*512 to keep fp16 operands in normal range
#define W_INV_SCALE (1.0f / 512.0f)

#define TILE_M 128
#define TILE_N 64
#define KCHUNK 64                  // fp16 K elements per stage = 128B per row
#define NCHUNKS (K_DIM / KCHUNK)   // 64
#define NSTAGES 3
#define STAGE_A_BYTES (TILE_M * 128)          // 16384
#define STAGE_B_BYTES (TILE_N * 128)          // 8192
#define STAGE_BYTES (STAGE_A_BYTES + STAGE_B_BYTES)   // 24576
#define SMEM_TOTAL (NSTAGES * STAGE_BYTES)    // 73728 -> 3 CTAs/SM (221KB)

// Merged precompute grid split: W blocks FIRST (longest-job-first scheduling)
#define WCOMP_BLOCKS 1024          // (16 i-tiles of 256) x (64 o-tiles)
#define XPACK_BLOCKS 4096          // 16.7M elems / 16 per thread / 256 threads

// fp16 packed operands (x direct; W_tot * 512)
__device__ __align__(128) __half g_xh[(size_t)M_DIM * K_DIM];
__device__ __align__(128) __half g_wh[(size_t)N_DIM * K_DIM];

// ---------------- PTX helpers (sm_103 baseline ISA only) ----------------

__device__ __forceinline__ uint32_t smem_u32(const void* p) {
    uint32_t a;
    asm("{ .reg .u64 t; cvta.to.shared.u64 t, %1; cvt.u32.u64 %0, t; }"
        : "=r"(a) : "l"(p));
    return a;
}

__device__ __forceinline__ void ldsm4(uint32_t* r, uint32_t addr) {
    asm volatile("ldmatrix.sync.aligned.m8n8.x4.shared.b16 {%0,%1,%2,%3}, [%4];"
                 : "=r"(r[0]), "=r"(r[1]), "=r"(r[2]), "=r"(r[3]) : "r"(addr));
}

__device__ __forceinline__ void mma16816(float* c, const uint32_t* a,
                                         const uint32_t* b) {
    asm volatile(
        "mma.sync.aligned.m16n8k16.row.col.f32.f16.f16.f32 "
        "{%0,%1,%2,%3}, {%4,%5,%6,%7}, {%8,%9}, {%0,%1,%2,%3};"
        : "+f"(c[0]), "+f"(c[1]), "+f"(c[2]), "+f"(c[3])
        : "r"(a[0]), "r"(a[1]), "r"(a[2]), "r"(a[3]), "r"(b[0]), "r"(b[1]));
}

__device__ __forceinline__ void cp_async16(uint32_t dst, const void* src) {
    asm volatile("cp.async.cg.shared.global [%0], [%1], 16;"
                 :: "r"(dst), "l"(src));
}
#define CP_COMMIT() asm volatile("cp.async.commit_group;" ::: "memory")
#define CP_WAIT1()  asm volatile("cp.async.wait_group 1;" ::: "memory")

// ---------------- Merged precompute kernel (R9 measured-best) ----------------
// Blocks [0, WCOMP_BLOCKS): build W_tot*512 (FMA-bound, long) -- scheduled first
// Blocks [WCOMP_BLOCKS, ...): pack x -> fp16, 16 elems/thread for MLP

__global__ void precomp_all(const float* __restrict__ x,
                            const float* __restrict__ weight,
                            const float* __restrict__ scale_A,
                            const float* __restrict__ scale_B,
                            const float* __restrict__ g,
                            const float* __restrict__ lora_A,
                            const float* __restrict__ lora_B) {
    int b = blockIdx.x;
    int t = threadIdx.x;

    if (b >= WCOMP_BLOCKS) {
        // ---- x pack: 16 fp32 -> 16 fp16 per thread (4 independent float4 loads) ----
        int idx = ((b - WCOMP_BLOCKS) * 256 + t) * 4;   // float4 index, < 4194304
        float4 v[4];
#pragma unroll
        for (int u = 0; u < 4; u++)
            v[u] = reinterpret_cast<const float4*>(x)[idx + u];
#pragma unroll
        for (int u = 0; u < 4; u++) {
            __half2 h0 = __floats2half2_rn(v[u].x, v[u].y);
            __half2 h1 = __floats2half2_rn(v[u].z, v[u].w);
            uint2 pk;
            pk.x = *reinterpret_cast<uint32_t*>(&h0);
            pk.y = *reinterpret_cast<uint32_t*>(&h1);
            reinterpret_cast<uint2*>(g_xh)[idx + u] = pk;
        }
        return;
    }

    // ---- W_tot compute (scalar per-i; low register pressure) ----
    int bx = b & 15;                 // 16 i-tiles of 256
    int by = b >> 4;                 // 64 o-tiles of 64

    __shared__ float ag[64][8];
    __shared__ float lb[64][16];
    int i0 = bx * 256;
    int o0 = by * 64;

    for (int u = t; u < 64 * 8; u += 256) {
        int ol = u >> 3, k = u & 7;
        ag[ol][k] = scale_A[(size_t)(o0 + ol) * RANK + k] * g[k];
    }
    for (int u = t; u < 64 * 16; u += 256) {
        int ol = u >> 4, r = u & 15;
        lb[ol][r] = lora_B[(size_t)(o0 + ol) * LORA_R + r] * LORA_SCALING_C;
    }
    __syncthreads();

    int i = i0 + t;
    float sb[8], la[16];
#pragma unroll
    for (int k = 0; k < 8; k++) sb[k] = scale_B[(size_t)k * K_DIM + i];
#pragma unroll
    for (int r = 0; r < 16; r++) la[r] = lora_A[(size_t)r * K_DIM + i];

#pragma unroll 8
    for (int ol = 0; ol < 64; ol++) {
        int o = o0 + ol;
        float S = 0.0f, L = 0.0f;
#pragma unroll
        for (int k = 0; k < 8; k++) S = fmaf(ag[ol][k], sb[k], S);
#pragma unroll
        for (int r = 0; r < 16; r++) L = fmaf(lb[ol][r], la[r], L);
        float w = weight[(size_t)o * K_DIM + i];
        float tot = fmaf(w, S, L) * W_SCALE;
        g_wh[(size_t)o * K_DIM + i] = __float2half_rn(tot);
    }
}

// ---------------- GEMM kernel (mma.sync fp16, CTA tile 128x64, occ 3) ----------
// 128 threads, 4 warps in 2x2 grid (warp tile 64x32); occupancy 3.
// Prefetch split: A-tile cp.asyncs after k-step 0, B-tile cp.asyncs after
// k-step 1, one commit per chunk. Spreads the LSU burst over two MMA windows.

__global__ void __launch_bounds__(128, 3) lora_gemm(float* __restrict__ out) {
    extern __shared__ char smem[];
    uint32_t sb = smem_u32(smem);
    int tid = threadIdx.x;
    int wid = tid >> 5;
    int lane = tid & 31;
    int warp_m = wid & 1;   // 2 m-blocks of 64
    int warp_n = wid >> 1;  // 2 n-blocks of 32
    int n0 = blockIdx.x * TILE_N;
    int m0 = blockIdx.y * TILE_M;

    // Per-thread cp.async addressing (one base each for A and B)
    int row0 = tid >> 3;          // 0..15
    int cc = tid & 7;             // 16B column
    uint32_t dOff = (uint32_t)(row0 * 128 + ((cc * 16) ^ ((row0 & 7) << 4)));
    const char* aSrc = reinterpret_cast<const char*>(g_xh)
                       + (size_t)(m0 + row0) * 8192 + cc * 16;
    const char* bSrc = reinterpret_cast<const char*>(g_wh)
                       + (size_t)(n0 + row0) * 8192 + cc * 16;
    // part stride: +16 rows = +2048B smem, +131072B global

    // ldmatrix lane addressing (swizzle: col16 ^= (row&7)<<4)
    uint32_t sx   = (uint32_t)((lane & 7) << 4);
    uint32_t aOff = (uint32_t)((warp_m * 64 + (lane & 15)) * 128);
    uint32_t aSel = (uint32_t)((lane >> 4) << 4);          // 0 or 16
    uint32_t bOff = (uint32_t)((warp_n * 32 + (lane & 7) + ((lane >> 4) << 3)) * 128);
    uint32_t bSel = (uint32_t)(((lane >> 3) & 1) << 4);    // 0 or 16

    float acc[4][4][4];
#pragma unroll
    for (int i = 0; i < 4; i++)
#pragma unroll
        for (int j = 0; j < 4; j++)
#pragma unroll
            for (int q = 0; q < 4; q++) acc[i][j][q] = 0.0f;

    // Prologue: chunks 0,1 into stages 0,1
#pragma unroll
    for (int s = 0; s < NSTAGES - 1; s++) {
        uint32_t sA = sb + s * STAGE_BYTES + dOff;
        uint32_t sBs = sA + STAGE_A_BYTES;
#pragma unroll
        for (int p = 0; p < 8; p++) cp_async16(sA + p * 2048, aSrc + (size_t)p * 131072);
#pragma unroll
        for (int p = 0; p < 4; p++) cp_async16(sBs + p * 2048, bSrc + (size_t)p * 131072);
        CP_COMMIT();
        aSrc += 128;
        bSrc += 128;
    }

    int stage = 0;
    int nstage = NSTAGES - 1;
    for (int chunk = 0; chunk < NCHUNKS; chunk++) {
        CP_WAIT1();            // chunk's group complete (<=1 outstanding beyond it)
        __syncthreads();       // also guards reuse of stage (chunk-1)

        uint32_t sA = sb + stage * STAGE_BYTES;
        uint32_t sB = sA + STAGE_A_BYTES;
        bool do_pf = (chunk + NSTAGES - 1 < NCHUNKS);
        uint32_t pA = sb + nstage * STAGE_BYTES + dOff;
        uint32_t pB = pA + STAGE_A_BYTES;

        // ---- k-step 0 (tensor pipe starts immediately after barrier) ----
        {
            uint32_t Af[4][4], Bf[2][4];
#pragma unroll
            for (int i = 0; i < 4; i++)
                ldsm4(Af[i], sA + aOff + i * 2048 + (aSel ^ sx));
#pragma unroll
            for (int p = 0; p < 2; p++)
                ldsm4(Bf[p], sB + bOff + p * 2048 + (bSel ^ sx));
#pragma unroll
            for (int i = 0; i < 4; i++)
#pragma unroll
                for (int j = 0; j < 4; j++)
                    mma16816(acc[i][j], Af[i], &Bf[j >> 1][(j & 1) * 2]);
        }

        // ---- prefetch A-tile of chunk+2 while tensor pipe is busy ----
        if (do_pf) {
#pragma unroll
            for (int p = 0; p < 8; p++) cp_async16(pA + p * 2048, aSrc + (size_t)p * 131072);
        }

        // ---- k-step 1 ----
        {
            uint32_t Af[4][4], Bf[2][4];
#pragma unroll
            for (int i = 0; i < 4; i++)
                ldsm4(Af[i], sA + aOff + i * 2048 + ((32u + aSel) ^ sx));
#pragma unroll
            for (int p = 0; p < 2; p++)
                ldsm4(Bf[p], sB + bOff + p * 2048 + ((32u + bSel) ^ sx));
#pragma unroll
            for (int i = 0; i < 4; i++)
#pragma unroll
                for (int j = 0; j < 4; j++)
                    mma16816(acc[i][j], Af[i], &Bf[j >> 1][(j & 1) * 2]);
        }

        // ---- prefetch B-tile of chunk+2, then commit the group ----
        if (do_pf) {
#pragma unroll
            for (int p = 0; p < 4; p++) cp_async16(pB + p * 2048, bSrc + (size_t)p * 131072);
            aSrc += 128;
            bSrc += 128;
        }
        CP_COMMIT();

        // ---- k-steps 2..3 ----
#pragma unroll
        for (int s = 2; s < 4; s++) {
            uint32_t Af[4][4], Bf[2][4];
            uint32_t cb = (uint32_t)(s * 32);
#pragma unroll
            for (int i = 0; i < 4; i++)
                ldsm4(Af[i], sA + aOff + i * 2048 + ((cb + aSel) ^ sx));
#pragma unroll
            for (int p = 0; p < 2; p++)
                ldsm4(Bf[p], sB + bOff + p * 2048 + ((cb + bSel) ^ sx));
#pragma unroll
            for (int i = 0; i < 4; i++)
#pragma unroll
                for (int j = 0; j < 4; j++)
                    mma16816(acc[i][j], Af[i], &Bf[j >> 1][(j & 1) * 2]);
        }

        if (++stage == NSTAGES) stage = 0;
        if (++nstage == NSTAGES) nstage = 0;
    }

    // Epilogue: scale by 1/512 and store.
    // Fragment: c0,c1 at (row lane/4, col 2*(lane%4)+{0,1}), c2,c3 at row+8.
    int r0 = m0 + warp_m * 64 + (lane >> 2);
    int c0 = n0 + warp_n * 32 + (lane & 3) * 2;
#pragma unroll
    for (int i = 0; i < 4; i++) {
#pragma unroll
        for (int j = 0; j < 4; j++) {
            float* p0 = out + (size_t)(r0 + i * 16) * N_DIM + (c0 + j * 8);
            float* p1 = out + (size_t)(r0 + i * 16 + 8) * N_DIM + (c0 + j * 8);
            float2 v0 = make_float2(acc[i][j][0] * W_INV_SCALE,
                                    acc[i][j][1] * W_INV_SCALE);
            float2 v1 = make_float2(acc[i][j][2] * W_INV_SCALE,
                                    acc[i][j][3] * W_INV_SCALE);
            *reinterpret_cast<float2*>(p0) = v0;
            *reinterpret_cast<float2*>(p1) = v1;
        }
    }
}

// ---------------- Launch ----------------

extern "C" void kernel_launch(void* const* d_in, const int* in_sizes, int n_in,
                              void* d_out, int out_size) {
    (void)in_sizes; (void)n_in; (void)out_size;
    const float* x       = (const float*)d_in[0];
    const float* weight  = (const float*)d_in[1];
    const float* scale_A = (const float*)d_in[2];
    const float* scale_B = (const float*)d_in[3];
    const float* g       = (const float*)d_in[4];
    const float* lora_A  = (const float*)d_in[5];
    const float* lora_B  = (const float*)d_in[6];
    float* out = (float*)d_out;

    cudaFuncSetAttribute(lora_gemm, cudaFuncAttributeMaxDynamicSharedMemorySize,
                         SMEM_TOTAL);

    precomp_all<<<WCOMP_BLOCKS + XPACK_BLOCKS, 256>>>(x, weight, scale_A, scale_B,
                                                      g, lora_A, lora_B);
    lora_gemm<<<dim3(N_DIM / TILE_N, M_DIM / TILE_M), 128, SMEM_TOTAL>>>(out);
}

// round 15
// speedup vs baseline: 1.5124x; 1.0245x over previous
#include <cuda_runtime.h>
#include <cuda_bf16.h>
#include <cuda_fp16.h>
#include <cstdint>

// Problem dims (fixed by the dataset)
#define M_DIM 4096   // B*S tokens
#define N_DIM 4096   // OUT
#define K_DIM 4096   // IN
#define RANK 8
#define LORA_R 16
#define LORA_SCALING_C 1.0f  // 16.0/16

#define W_SCALE 512.0f       // W packed as W*512 to keep fp16 operands in normal range
#define W_INV_SCALE (1.0f / 512.0f)

#define TILE_M 128
#define TILE_N 64
#define KCHUNK 64                  // fp16 K elements per stage = 128B per row
#define NCHUNKS (K_DIM / KCHUNK)   // 64
#define NSTAGES 3
#define STAGE_A_BYTES (TILE_M * 128)          // 16384
#define STAGE_B_BYTES (TILE_N * 128)          // 8192
#define STAGE_BYTES (STAGE_A_BYTES + STAGE_B_BYTES)   // 24576
#define SMEM_TOTAL (NSTAGES * STAGE_BYTES)    // 73728 -> 3 CTAs/SM (221KB)

// Merged precompute grid split: W blocks FIRST (longest-job-first scheduling)
#define WCOMP_BLOCKS 1024          // (16 i-tiles of 256) x (64 o-tiles)
#define XPACK_BLOCKS 4096          // 16.7M elems / 16 per thread / 256 threads

// fp16 packed operands (x direct; W_tot * 512)
__device__ __align__(128) __half g_xh[(size_t)M_DIM * K_DIM];
__device__ __align__(128) __half g_wh[(size_t)N_DIM * K_DIM];

// ---------------- PTX helpers (sm_103 baseline ISA only) ----------------

__device__ __forceinline__ uint32_t smem_u32(const void* p) {
    uint32_t a;
    asm("{ .reg .u64 t; cvta.to.shared.u64 t, %1; cvt.u32.u64 %0, t; }"
        : "=r"(a) : "l"(p));
    return a;
}

__device__ __forceinline__ void ldsm4(uint32_t* r, uint32_t addr) {
    asm volatile("ldmatrix.sync.aligned.m8n8.x4.shared.b16 {%0,%1,%2,%3}, [%4];"
                 : "=r"(r[0]), "=r"(r[1]), "=r"(r[2]), "=r"(r[3]) : "r"(addr));
}

__device__ __forceinline__ void mma16816(float* c, const uint32_t* a,
                                         const uint32_t* b) {
    asm volatile(
        "mma.sync.aligned.m16n8k16.row.col.f32.f16.f16.f32 "
        "{%0,%1,%2,%3}, {%4,%5,%6,%7}, {%8,%9}, {%0,%1,%2,%3};"
        : "+f"(c[0]), "+f"(c[1]), "+f"(c[2]), "+f"(c[3])
        : "r"(a[0]), "r"(a[1]), "r"(a[2]), "r"(a[3]), "r"(b[0]), "r"(b[1]));
}

__device__ __forceinline__ void cp_async16(uint32_t dst, const void* src) {
    asm volatile("cp.async.cg.shared.global [%0], [%1], 16;"
                 :: "r"(dst), "l"(src));
}
#define CP_COMMIT() asm volatile("cp.async.commit_group;" ::: "memory")
#define CP_WAIT1()  asm volatile("cp.async.wait_group 1;" ::: "memory")

// ---------------- Merged precompute kernel (R9 measured-best) ----------------
// Blocks [0, WCOMP_BLOCKS): build W_tot*512 (FMA-bound, long) -- scheduled first
// Blocks [WCOMP_BLOCKS, ...): pack x -> fp16, 16 elems/thread for MLP

__global__ void precomp_all(const float* __restrict__ x,
                            const float* __restrict__ weight,
                            const float* __restrict__ scale_A,
                            const float* __restrict__ scale_B,
                            const float* __restrict__ g,
                            const float* __restrict__ lora_A,
                            const float* __restrict__ lora_B) {
    int b = blockIdx.x;
    int t = threadIdx.x;

    if (b >= WCOMP_BLOCKS) {
        // ---- x pack: 16 fp32 -> 16 fp16 per thread (4 independent float4 loads) ----
        int idx = ((b - WCOMP_BLOCKS) * 256 + t) * 4;   // float4 index, < 4194304
        float4 v[4];
#pragma unroll
        for (int u = 0; u < 4; u++)
            v[u] = reinterpret_cast<const float4*>(x)[idx + u];
#pragma unroll
        for (int u = 0; u < 4; u++) {
            __half2 h0 = __floats2half2_rn(v[u].x, v[u].y);
            __half2 h1 = __floats2half2_rn(v[u].z, v[u].w);
            uint2 pk;
            pk.x = *reinterpret_cast<uint32_t*>(&h0);
            pk.y = *reinterpret_cast<uint32_t*>(&h1);
            reinterpret_cast<uint2*>(g_xh)[idx + u] = pk;
        }
        return;
    }

    // ---- W_tot compute (scalar per-i; low register pressure) ----
    int bx = b & 15;                 // 16 i-tiles of 256
    int by = b >> 4;                 // 64 o-tiles of 64

    __shared__ float ag[64][8];
    __shared__ float lb[64][16];
    int i0 = bx * 256;
    int o0 = by * 64;

    for (int u = t; u < 64 * 8; u += 256) {
        int ol = u >> 3, k = u & 7;
        ag[ol][k] = scale_A[(size_t)(o0 + ol) * RANK + k] * g[k];
    }
    for (int u = t; u < 64 * 16; u += 256) {
        int ol = u >> 4, r = u & 15;
        lb[ol][r] = lora_B[(size_t)(o0 + ol) * LORA_R + r] * LORA_SCALING_C;
    }
    __syncthreads();

    int i = i0 + t;
    float sb[8], la[16];
#pragma unroll
    for (int k = 0; k < 8; k++) sb[k] = scale_B[(size_t)k * K_DIM + i];
#pragma unroll
    for (int r = 0; r < 16; r++) la[r] = lora_A[(size_t)r * K_DIM + i];

#pragma unroll 8
    for (int ol = 0; ol < 64; ol++) {
        int o = o0 + ol;
        float S = 0.0f, L = 0.0f;
#pragma unroll
        for (int k = 0; k < 8; k++) S = fmaf(ag[ol][k], sb[k], S);
#pragma unroll
        for (int r = 0; r < 16; r++) L = fmaf(lb[ol][r], la[r], L);
        float w = weight[(size_t)o * K_DIM + i];
        float tot = fmaf(w, S, L) * W_SCALE;
        g_wh[(size_t)o * K_DIM + i] = __float2half_rn(tot);
    }
}

// ---------------- GEMM kernel (mma.sync fp16, CTA tile 128x64, occ 3) ----------
// 128 threads, 4 warps in 2x2 grid (warp tile 64x32); occupancy 3.
// Single prefetch burst issued AFTER k-step 0 (R11 measured-best placement:
// the LSU burst drains behind 16 back-to-back MMAs instead of stalling the
// LDSM window of the next k-step).

__global__ void __launch_bounds__(128, 3) lora_gemm(float* __restrict__ out) {
    extern __shared__ char smem[];
    uint32_t sb = smem_u32(smem);
    int tid = threadIdx.x;
    int wid = tid >> 5;
    int lane = tid & 31;
    int warp_m = wid & 1;   // 2 m-blocks of 64
    int warp_n = wid >> 1;  // 2 n-blocks of 32
    int n0 = blockIdx.x * TILE_N;
    int m0 = blockIdx.y * TILE_M;

    // Per-thread cp.async addressing (one base each for A and B)
    int row0 = tid >> 3;          // 0..15
    int cc = tid & 7;             // 16B column
    uint32_t dOff = (uint32_t)(row0 * 128 + ((cc * 16) ^ ((row0 & 7) << 4)));
    const char* aSrc = reinterpret_cast<const char*>(g_xh)
                       + (size_t)(m0 + row0) * 8192 + cc * 16;
    const char* bSrc = reinterpret_cast<const char*>(g_wh)
                       + (size_t)(n0 + row0) * 8192 + cc * 16;
    // part stride: +16 rows = +2048B smem, +131072B global

    // ldmatrix lane addressing (swizzle: col16 ^= (row&7)<<4)
    uint32_t sx   = (uint32_t)((lane & 7) << 4);
    uint32_t aOff = (uint32_t)((warp_m * 64 + (lane & 15)) * 128);
    uint32_t aSel = (uint32_t)((lane >> 4) << 4);          // 0 or 16
    uint32_t bOff = (uint32_t)((warp_n * 32 + (lane & 7) + ((lane >> 4) << 3)) * 128);
    uint32_t bSel = (uint32_t)(((lane >> 3) & 1) << 4);    // 0 or 16

    float acc[4][4][4];
#pragma unroll
    for (int i = 0; i < 4; i++)
#pragma unroll
        for (int j = 0; j < 4; j++)
#pragma unroll
            for (int q = 0; q < 4; q++) acc[i][j][q] = 0.0f;

    // Prologue: chunks 0,1 into stages 0,1
#pragma unroll
    for (int s = 0; s < NSTAGES - 1; s++) {
        uint32_t sA = sb + s * STAGE_BYTES + dOff;
        uint32_t sBs = sA + STAGE_A_BYTES;
#pragma unroll
        for (int p = 0; p < 8; p++) cp_async16(sA + p * 2048, aSrc + (size_t)p * 131072);
#pragma unroll
        for (int p = 0; p < 4; p++) cp_async16(sBs + p * 2048, bSrc + (size_t)p * 131072);
        CP_COMMIT();
        aSrc += 128;
        bSrc += 128;
    }

    int stage = 0;
    int nstage = NSTAGES - 1;
    for (int chunk = 0; chunk < NCHUNKS; chunk++) {
        CP_WAIT1();            // chunk's group complete (<=1 outstanding beyond it)
        __syncthreads();       // also guards reuse of stage (chunk-1)

        uint32_t sA = sb + stage * STAGE_BYTES;
        uint32_t sB = sA + STAGE_A_BYTES;

        // ---- k-step 0 first (tensor pipe starts immediately after barrier) ----
        {
            uint32_t Af[4][4], Bf[2][4];
#pragma unroll
            for (int i = 0; i < 4; i++)
                ldsm4(Af[i], sA + aOff + i * 2048 + (aSel ^ sx));
#pragma unroll
            for (int p = 0; p < 2; p++)
                ldsm4(Bf[p], sB + bOff + p * 2048 + (bSel ^ sx));
#pragma unroll
            for (int i = 0; i < 4; i++)
#pragma unroll
                for (int j = 0; j < 4; j++)
                    mma16816(acc[i][j], Af[i], &Bf[j >> 1][(j & 1) * 2]);
        }

        // ---- prefetch chunk+2 while tensor pipe is busy ----
        if (chunk + NSTAGES - 1 < NCHUNKS) {
            uint32_t pA = sb + nstage * STAGE_BYTES + dOff;
            uint32_t pB = pA + STAGE_A_BYTES;
#pragma unroll
            for (int p = 0; p < 8; p++) cp_async16(pA + p * 2048, aSrc + (size_t)p * 131072);
#pragma unroll
            for (int p = 0; p < 4; p++) cp_async16(pB + p * 2048, bSrc + (size_t)p * 131072);
            aSrc += 128;
            bSrc += 128;
        }
        CP_COMMIT();

        // ---- k-steps 1..3 ----
#pragma unroll
        for (int s = 1; s < 4; s++) {
            uint32_t Af[4][4], Bf[2][4];
            uint32_t cb = (uint32_t)(s * 32);
#pragma unroll
            for (int i = 0; i < 4; i++)
                ldsm4(Af[i], sA + aOff + i * 2048 + ((cb + aSel) ^ sx));
#pragma unroll
            for (int p = 0; p < 2; p++)
                ldsm4(Bf[p], sB + bOff + p * 2048 + ((cb + bSel) ^ sx));
#pragma unroll
            for (int i = 0; i < 4; i++)
#pragma unroll
                for (int j = 0; j < 4; j++)
                    mma16816(acc[i][j], Af[i], &Bf[j >> 1][(j & 1) * 2]);
        }

        if (++stage == NSTAGES) stage = 0;
        if (++nstage == NSTAGES) nstage = 0;
    }

    // Epilogue: scale by 1/512 and store.
    // Fragment: c0,c1 at (row lane/4, col 2*(lane%4)+{0,1}), c2,c3 at row+8.
    int r0 = m0 + warp_m * 64 + (lane >> 2);
    int c0 = n0 + warp_n * 32 + (lane & 3) * 2;
#pragma unroll
    for (int i = 0; i < 4; i++) {
#pragma unroll
        for (int j = 0; j < 4; j++) {
            float* p0 = out + (size_t)(r0 + i * 16) * N_DIM + (c0 + j * 8);
            float* p1 = out + (size_t)(r0 + i * 16 + 8) * N_DIM + (c0 + j * 8);
            float2 v0 = make_float2(acc[i][j][0] * W_INV_SCALE,
                                    acc[i][j][1] * W_INV_SCALE);
            float2 v1 = make_float2(acc[i][j][2] * W_INV_SCALE,
                                    acc[i][j][3] * W_INV_SCALE);
            *reinterpret_cast<float2*>(p0) = v0;
            *reinterpret_cast<float2*>(p1) = v1;
        }
    }
}

// ---------------- Launch ----------------

extern "C" void kernel_launch(void* const* d_in, const int* in_sizes, int n_in,
                              void* d_out, int out_size) {
    (void)in_sizes; (void)n_in; (void)out_size;
    const float* x       = (const float*)d_in[0];
    const float* weight  = (const float*)d_in[1];
    const float* scale_A = (const float*)d_in[2];
    const float* scale_B = (const float*)d_in[3];
    const float* g       = (const float*)d_in[4];
    const float* lora_A  = (const float*)d_in[5];
    const float* lora_B  = (const float*)d_in[6];
    float* out = (float*)d_out;

    cudaFuncSetAttribute(lora_gemm, cudaFuncAttributeMaxDynamicSharedMemorySize,
                         SMEM_TOTAL);

    precomp_all<<<WCOMP_BLOCKS + XPACK_BLOCKS, 256>>>(x, weight, scale_A, scale_B,
                                                      g, lora_A, lora_B);
    lora_gemm<<<dim3(N_DIM / TILE_N, M_DIM / TILE_M), 128, SMEM_TOTAL>>>(out);
}

// round 16
// speedup vs baseline: 1.5160x; 1.0024x over previous
#include <cuda_runtime.h>
#include <cuda_bf16.h>
#include <cuda_fp16.h>
#include <cstdint>

// Problem dims (fixed by the dataset)
#define M_DIM 4096   // B*S tokens
#define N_DIM 4096   // OUT
#define K_DIM 4096   // IN
#define RANK 8
#define LORA_R 16
#define LORA_SCALING_C 1.0f  // 16.0/16

#define W_SCALE 512.0f       // W packed as W*512 to keep fp16 operands in normal range
#define W_INV_SCALE (1.0f / 512.0f)

#define TILE_M 128
#define TILE_N 64
#define KCHUNK 64                  // fp16 K elements per stage = 128B per row
#define NCHUNKS (K_DIM / KCHUNK)   // 64
#define NSTAGES 3
#define STAGE_A_BYTES (TILE_M * 128)          // 16384
#define STAGE_B_BYTES (TILE_N * 128)          // 8192
#define STAGE_BYTES (STAGE_A_BYTES + STAGE_B_BYTES)   // 24576
#define SMEM_TOTAL (NSTAGES * STAGE_BYTES)    // 73728 -> 3 CTAs/SM (221KB)

// Merged precompute grid split: W blocks FIRST (longest-job-first scheduling)
// W o-tile split to 32 rows for finer interleave with x-pack blocks.
#define WCOMP_BLOCKS 2048          // (16 i-tiles of 256) x (128 o-tiles of 32)
#define XPACK_BLOCKS 4096          // 16.7M elems / 16 per thread / 256 threads

// fp16 packed operands (x direct; W_tot * 512)
__device__ __align__(128) __half g_xh[(size_t)M_DIM * K_DIM];
__device__ __align__(128) __half g_wh[(size_t)N_DIM * K_DIM];

// ---------------- PTX helpers (sm_103 baseline ISA only) ----------------

__device__ __forceinline__ uint32_t smem_u32(const void* p) {
    uint32_t a;
    asm("{ .reg .u64 t; cvta.to.shared.u64 t, %1; cvt.u32.u64 %0, t; }"
        : "=r"(a) : "l"(p));
    return a;
}

__device__ __forceinline__ void ldsm4(uint32_t* r, uint32_t addr) {
    asm volatile("ldmatrix.sync.aligned.m8n8.x4.shared.b16 {%0,%1,%2,%3}, [%4];"
                 : "=r"(r[0]), "=r"(r[1]), "=r"(r[2]), "=r"(r[3]) : "r"(addr));
}

__device__ __forceinline__ void mma16816(float* c, const uint32_t* a,
                                         const uint32_t* b) {
    asm volatile(
        "mma.sync.aligned.m16n8k16.row.col.f32.f16.f16.f32 "
        "{%0,%1,%2,%3}, {%4,%5,%6,%7}, {%8,%9}, {%0,%1,%2,%3};"
        : "+f"(c[0]), "+f"(c[1]), "+f"(c[2]), "+f"(c[3])
        : "r"(a[0]), "r"(a[1]), "r"(a[2]), "r"(a[3]), "r"(b[0]), "r"(b[1]));
}

__device__ __forceinline__ void cp_async16(uint32_t dst, const void* src) {
    asm volatile("cp.async.cg.shared.global [%0], [%1], 16;"
                 :: "r"(dst), "l"(src));
}
#define CP_COMMIT() asm volatile("cp.async.commit_group;" ::: "memory")
#define CP_WAIT1()  asm volatile("cp.async.wait_group 1;" ::: "memory")

// ---------------- Merged precompute kernel ----------------
// Blocks [0, WCOMP_BLOCKS): build W_tot*512, 32 o-rows per block
// Blocks [WCOMP_BLOCKS, ...): pack x -> fp16, 16 elems/thread

__global__ void precomp_all(const float* __restrict__ x,
                            const float* __restrict__ weight,
                            const float* __restrict__ scale_A,
                            const float* __restrict__ scale_B,
                            const float* __restrict__ g,
                            const float* __restrict__ lora_A,
                            const float* __restrict__ lora_B) {
    int b = blockIdx.x;
    int t = threadIdx.x;

    if (b >= WCOMP_BLOCKS) {
        // ---- x pack: 16 fp32 -> 16 fp16 per thread (4 independent float4 loads) ----
        int idx = ((b - WCOMP_BLOCKS) * 256 + t) * 4;   // float4 index, < 4194304
        float4 v[4];
#pragma unroll
        for (int u = 0; u < 4; u++)
            v[u] = reinterpret_cast<const float4*>(x)[idx + u];
#pragma unroll
        for (int u = 0; u < 4; u++) {
            __half2 h0 = __floats2half2_rn(v[u].x, v[u].y);
            __half2 h1 = __floats2half2_rn(v[u].z, v[u].w);
            uint2 pk;
            pk.x = *reinterpret_cast<uint32_t*>(&h0);
            pk.y = *reinterpret_cast<uint32_t*>(&h1);
            reinterpret_cast<uint2*>(g_xh)[idx + u] = pk;
        }
        return;
    }

    // ---- W_tot compute (scalar per-i; 32 o-rows per block) ----
    int bx = b & 15;                 // 16 i-tiles of 256
    int by = b >> 4;                 // 128 o-tiles of 32

    __shared__ float ag[32][8];
    __shared__ float lb[32][16];
    int i0 = bx * 256;
    int o0 = by * 32;

    for (int u = t; u < 32 * 8; u += 256) {
        int ol = u >> 3, k = u & 7;
        ag[ol][k] = scale_A[(size_t)(o0 + ol) * RANK + k] * g[k];
    }
    for (int u = t; u < 32 * 16; u += 256) {
        int ol = u >> 4, r = u & 15;
        lb[ol][r] = lora_B[(size_t)(o0 + ol) * LORA_R + r] * LORA_SCALING_C;
    }
    __syncthreads();

    int i = i0 + t;
    float sb[8], la[16];
#pragma unroll
    for (int k = 0; k < 8; k++) sb[k] = scale_B[(size_t)k * K_DIM + i];
#pragma unroll
    for (int r = 0; r < 16; r++) la[r] = lora_A[(size_t)r * K_DIM + i];

#pragma unroll 8
    for (int ol = 0; ol < 32; ol++) {
        int o = o0 + ol;
        float S = 0.0f, L = 0.0f;
#pragma unroll
        for (int k = 0; k < 8; k++) S = fmaf(ag[ol][k], sb[k], S);
#pragma unroll
        for (int r = 0; r < 16; r++) L = fmaf(lb[ol][r], la[r], L);
        float w = weight[(size_t)o * K_DIM + i];
        float tot = fmaf(w, S, L) * W_SCALE;
        g_wh[(size_t)o * K_DIM + i] = __float2half_rn(tot);
    }
}

// ---------------- GEMM kernel (mma.sync fp16, CTA tile 128x64, occ 3) ----------
// 128 threads, 4 warps in 2x2 grid (warp tile 64x32); occupancy 3.
// Fragment double-buffering: k-step s+1's ldmatrix issues before k-step s's
// MMAs, so LDSM latency is covered by the tensor pipe instead of stalling it.
// Single cp.async prefetch burst after the first MMA block (R11 placement).

__device__ __forceinline__ void ldsm_kstep(uint32_t Af[4][4], uint32_t Bf[2][4],
                                           uint32_t sA, uint32_t sB,
                                           uint32_t aOff, uint32_t bOff,
                                           uint32_t aSel, uint32_t bSel,
                                           uint32_t sx, uint32_t cb) {
#pragma unroll
    for (int i = 0; i < 4; i++)
        ldsm4(Af[i], sA + aOff + i * 2048 + ((cb + aSel) ^ sx));
#pragma unroll
    for (int p = 0; p < 2; p++)
        ldsm4(Bf[p], sB + bOff + p * 2048 + ((cb + bSel) ^ sx));
}

__device__ __forceinline__ void mma_block(float acc[4][4][4],
                                          uint32_t Af[4][4], uint32_t Bf[2][4]) {
#pragma unroll
    for (int i = 0; i < 4; i++)
#pragma unroll
        for (int j = 0; j < 4; j++)
            mma16816(acc[i][j], Af[i], &Bf[j >> 1][(j & 1) * 2]);
}

__global__ void __launch_bounds__(128, 3) lora_gemm(float* __restrict__ out) {
    extern __shared__ char smem[];
    uint32_t sb = smem_u32(smem);
    int tid = threadIdx.x;
    int wid = tid >> 5;
    int lane = tid & 31;
    int warp_m = wid & 1;   // 2 m-blocks of 64
    int warp_n = wid >> 1;  // 2 n-blocks of 32
    int n0 = blockIdx.x * TILE_N;
    int m0 = blockIdx.y * TILE_M;

    // Per-thread cp.async addressing (one base each for A and B)
    int row0 = tid >> 3;          // 0..15
    int cc = tid & 7;             // 16B column
    uint32_t dOff = (uint32_t)(row0 * 128 + ((cc * 16) ^ ((row0 & 7) << 4)));
    const char* aSrc = reinterpret_cast<const char*>(g_xh)
                       + (size_t)(m0 + row0) * 8192 + cc * 16;
    const char* bSrc = reinterpret_cast<const char*>(g_wh)
                       + (size_t)(n0 + row0) * 8192 + cc * 16;
    // part stride: +16 rows = +2048B smem, +131072B global

    // ldmatrix lane addressing (swizzle: col16 ^= (row&7)<<4)
    uint32_t sx   = (uint32_t)((lane & 7) << 4);
    uint32_t aOff = (uint32_t)((warp_m * 64 + (lane & 15)) * 128);
    uint32_t aSel = (uint32_t)((lane >> 4) << 4);          // 0 or 16
    uint32_t bOff = (uint32_t)((warp_n * 32 + (lane & 7) + ((lane >> 4) << 3)) * 128);
    uint32_t bSel = (uint32_t)(((lane >> 3) & 1) << 4);    // 0 or 16

    float acc[4][4][4];
#pragma unroll
    for (int i = 0; i < 4; i++)
#pragma unroll
        for (int j = 0; j < 4; j++)
#pragma unroll
            for (int q = 0; q < 4; q++) acc[i][j][q] = 0.0f;

    // Prologue: chunks 0,1 into stages 0,1
#pragma unroll
    for (int s = 0; s < NSTAGES - 1; s++) {
        uint32_t sA = sb + s * STAGE_BYTES + dOff;
        uint32_t sBs = sA + STAGE_A_BYTES;
#pragma unroll
        for (int p = 0; p < 8; p++) cp_async16(sA + p * 2048, aSrc + (size_t)p * 131072);
#pragma unroll
        for (int p = 0; p < 4; p++) cp_async16(sBs + p * 2048, bSrc + (size_t)p * 131072);
        CP_COMMIT();
        aSrc += 128;
        bSrc += 128;
    }

    int stage = 0;
    int nstage = NSTAGES - 1;
    for (int chunk = 0; chunk < NCHUNKS; chunk++) {
        CP_WAIT1();            // chunk's group complete (<=1 outstanding beyond it)
        __syncthreads();       // also guards reuse of stage (chunk-1)

        uint32_t sA = sb + stage * STAGE_BYTES;
        uint32_t sB = sA + STAGE_A_BYTES;

        uint32_t Af[2][4][4], Bf[2][2][4];

        // ---- k-steps 0,1 fragments, then k-step 0 MMAs ----
        ldsm_kstep(Af[0], Bf[0], sA, sB, aOff, bOff, aSel, bSel, sx, 0);
        ldsm_kstep(Af[1], Bf[1], sA, sB, aOff, bOff, aSel, bSel, sx, 32);
        mma_block(acc, Af[0], Bf[0]);

        // ---- prefetch chunk+2 while tensor pipe is busy ----
        if (chunk + NSTAGES - 1 < NCHUNKS) {
            uint32_t pA = sb + nstage * STAGE_BYTES + dOff;
            uint32_t pB = pA + STAGE_A_BYTES;
#pragma unroll
            for (int p = 0; p < 8; p++) cp_async16(pA + p * 2048, aSrc + (size_t)p * 131072);
#pragma unroll
            for (int p = 0; p < 4; p++) cp_async16(pB + p * 2048, bSrc + (size_t)p * 131072);
            aSrc += 128;
            bSrc += 128;
        }
        CP_COMMIT();

        // ---- pipelined k-steps 1..3 ----
        ldsm_kstep(Af[0], Bf[0], sA, sB, aOff, bOff, aSel, bSel, sx, 64);
        mma_block(acc, Af[1], Bf[1]);
        ldsm_kstep(Af[1], Bf[1], sA, sB, aOff, bOff, aSel, bSel, sx, 96);
        mma_block(acc, Af[0], Bf[0]);
        mma_block(acc, Af[1], Bf[1]);

        if (++stage == NSTAGES) stage = 0;
        if (++nstage == NSTAGES) nstage = 0;
    }

    // Epilogue: scale by 1/512 and store.
    // Fragment: c0,c1 at (row lane/4, col 2*(lane%4)+{0,1}), c2,c3 at row+8.
    int r0 = m0 + warp_m * 64 + (lane >> 2);
    int c0 = n0 + warp_n * 32 + (lane & 3) * 2;
#pragma unroll
    for (int i = 0; i < 4; i++) {
#pragma unroll
        for (int j = 0; j < 4; j++) {
            float* p0 = out + (size_t)(r0 + i * 16) * N_DIM + (c0 + j * 8);
            float* p1 = out + (size_t)(r0 + i * 16 + 8) * N_DIM + (c0 + j * 8);
            float2 v0 = make_float2(acc[i][j][0] * W_INV_SCALE,
                                    acc[i][j][1] * W_INV_SCALE);
            float2 v1 = make_float2(acc[i][j][2] * W_INV_SCALE,
                                    acc[i][j][3] * W_INV_SCALE);
            *reinterpret_cast<float2*>(p0) = v0;
            *reinterpret_cast<float2*>(p1) = v1;
        }
    }
}

// ---------------- Launch ----------------

extern "C" void kernel_launch(void* const* d_in, const int* in_sizes, int n_in,
                              void* d_out, int out_size) {
    (void)in_sizes; (void)n_in; (void)out_size;
    const float* x       = (const float*)d_in[0];
    const float* weight  = (const float*)d_in[1];
    const float* scale_A = (const float*)d_in[2];
    const float* scale_B = (const float*)d_in[3];
    const float* g       = (const float*)d_in[4];
    const float* lora_A  = (const float*)d_in[5];
    const float* lora_B  = (const float*)d_in[6];
    float* out = (float*)d_out;

    cudaFuncSetAttribute(lora_gemm, cudaFuncAttributeMaxDynamicSharedMemorySize,
                         SMEM_TOTAL);

    precomp_all<<<WCOMP_BLOCKS + XPACK_BLOCKS, 256>>>(x, weight, scale_A, scale_B,
                                                      g, lora_A, lora_B);
    lora_gemm<<<dim3(N_DIM / TILE_N, M_DIM / TILE_M), 128, SMEM_TOTAL>>>(out);
}